// round 2
// baseline (speedup 1.0000x reference)
#include <cuda_runtime.h>

#define NHEAD 8
#define SEQ   4096
#define DIN   3
#define DH    8

// Scratch (allocation-free rule: __device__ globals).
// z[g][t] = float4( SCALE * (Wq^T Wk x2_t), SCALE * (bq . Wk x2_t) )
// v[g][t][h] = Wv x1_t + bv
__device__ float4 g_z[NHEAD * SEQ];
__device__ float  g_v[NHEAD * SEQ * DH];

// ---------------------------------------------------------------------------
// Precompute kernel: one thread per (g, t).
// ---------------------------------------------------------------------------
__global__ void precompute_kernel(const float* __restrict__ x1,
                                  const float* __restrict__ x2,
                                  const float* __restrict__ Wq,
                                  const float* __restrict__ bq,
                                  const float* __restrict__ Wk,
                                  const float* __restrict__ Wv,
                                  const float* __restrict__ bv) {
    int i = blockIdx.x * blockDim.x + threadIdx.x;   // i = g*SEQ + t
    if (i >= NHEAD * SEQ) return;

    const float SCALEF = 1448.1546878700492f;  // 2^10.5

    float X1[3], X2[3];
#pragma unroll
    for (int j = 0; j < 3; j++) { X1[j] = x1[i * 3 + j]; X2[j] = x2[i * 3 + j]; }

    // u_h = Wk[h] . x2 ;  y = Wq^T u ; w = bq . u
    float y0 = 0.f, y1 = 0.f, y2 = 0.f, w = 0.f;
#pragma unroll
    for (int h = 0; h < 8; h++) {
        float u = fmaf(Wk[h * 3 + 0], X2[0],
                  fmaf(Wk[h * 3 + 1], X2[1], Wk[h * 3 + 2] * X2[2]));
        y0 = fmaf(Wq[h * 3 + 0], u, y0);
        y1 = fmaf(Wq[h * 3 + 1], u, y1);
        y2 = fmaf(Wq[h * 3 + 2], u, y2);
        w  = fmaf(bq[h], u, w);
    }
    g_z[i] = make_float4(SCALEF * y0, SCALEF * y1, SCALEF * y2, SCALEF * w);

#pragma unroll
    for (int h = 0; h < 8; h++) {
        g_v[i * 8 + h] = fmaf(Wv[h * 3 + 0], X1[0],
                         fmaf(Wv[h * 3 + 1], X1[1],
                         fmaf(Wv[h * 3 + 2], X1[2], bv[h])));
    }
}

// ---------------------------------------------------------------------------
// Threefry2x32, PARTITIONABLE mode (modern JAX default):
// For element i of random_bits(key(42), 32, n): counter = (hi32(i), lo32(i))
// = (0, i) here (n = 2^27 < 2^32); output word = x0_out ^ x1_out.
// bernoulli(0.5): keep  <=>  uniform < 0.5  <=>  MSB(word) == 0.
// Key (k0, k1) = (0, 42); ks2 = 0x1BD11BDA ^ 0 ^ 42 = 0x1BD11BF0.
// ---------------------------------------------------------------------------
__device__ __forceinline__ unsigned rotl32(unsigned x, int r) {
    return __funnelshift_l(x, x, r);
}

__device__ __forceinline__ unsigned threefry_word(unsigned idx) {
    const unsigned K1 = 42u;
    const unsigned K2 = 0x1BD11BF0u;
    unsigned x0 = 0u;            // counter hi word + ks0 (= 0)
    unsigned x1 = idx + K1;      // counter lo word + ks1

#define TF_R(r)  { x0 += x1; x1 = rotl32(x1, r); x1 ^= x0; }
#define TF_G(a,b,c,d,j0,j1) TF_R(a) TF_R(b) TF_R(c) TF_R(d) x0 += (j0); x1 += (j1);
    TF_G(13, 15, 26,  6, K1,       K2 + 1u)
    TF_G(17, 29, 16, 24, K2,       0u + 2u)
    TF_G(13, 15, 26,  6, 0u,       K1 + 3u)
    TF_G(17, 29, 16, 24, K1,       K2 + 4u)
    TF_G(13, 15, 26,  6, K2,       0u + 5u)
#undef TF_G
#undef TF_R
    return x0 ^ x1;
}

// ---------------------------------------------------------------------------
// Main kernel: 1 thread per (g, s) row, online softmax over t with lazy
// exp/threefry/V-accumulate (only entries within 25 of the running max).
// ---------------------------------------------------------------------------
__global__ void attn_kernel(const float* __restrict__ x1,
                            float* __restrict__ out) {
    extern __shared__ float4 zs[];             // 4096 * 16B = 64 KB
    const int g = blockIdx.y;
    const int s = blockIdx.x * blockDim.x + threadIdx.x;

    const float4* zg = g_z + g * SEQ;
    for (int i = threadIdx.x; i < SEQ; i += blockDim.x) zs[i] = zg[i];
    __syncthreads();

    const int row = g * SEQ + s;
    const float a = x1[row * 3 + 0];
    const float b = x1[row * 3 + 1];
    const float c = x1[row * 3 + 2];
    const unsigned rowbase = (unsigned)row << 12;          // flat mask idx base, < 2^27
    const float* vg = g_v + (size_t)g * SEQ * DH;

    float m = -3.0e38f, l = 0.0f;
    float acc0 = 0.f, acc1 = 0.f, acc2 = 0.f, acc3 = 0.f;
    float acc4 = 0.f, acc5 = 0.f, acc6 = 0.f, acc7 = 0.f;

    for (int t = 0; t < SEQ; t += 4) {
        const float4 z0 = zs[t + 0];
        const float4 z1 = zs[t + 1];
        const float4 z2 = zs[t + 2];
        const float4 z3 = zs[t + 3];
        const float s0 = fmaf(a, z0.x, fmaf(b, z0.y, fmaf(c, z0.z, z0.w)));
        const float s1 = fmaf(a, z1.x, fmaf(b, z1.y, fmaf(c, z1.z, z1.w)));
        const float s2 = fmaf(a, z2.x, fmaf(b, z2.y, fmaf(c, z2.z, z2.w)));
        const float s3 = fmaf(a, z3.x, fmaf(b, z3.y, fmaf(c, z3.z, z3.w)));
        const float pm = fmaxf(fmaxf(s0, s1), fmaxf(s2, s3));

        if (pm > m - 25.0f) {                  // cold path: ~10 hits per row
            const float sv[4] = {s0, s1, s2, s3};
#pragma unroll
            for (int j = 0; j < 4; j++) {
                const float sj = sv[j];
                if (sj > m - 25.0f) {
                    float p;
                    if (sj > m) {
                        const float f = __expf(m - sj);
                        l *= f;
                        acc0 *= f; acc1 *= f; acc2 *= f; acc3 *= f;
                        acc4 *= f; acc5 *= f; acc6 *= f; acc7 *= f;
                        m = sj;
                        p = 1.0f;
                    } else {
                        p = __expf(sj - m);
                    }
                    l += p;   // denominator counts ALL surviving-exp terms (mask-independent)
                    const unsigned wbits = threefry_word(rowbase + (unsigned)(t + j));
                    if (!(wbits & 0x80000000u)) {          // keep (u < 0.5)
                        const float4* vp =
                            reinterpret_cast<const float4*>(vg + (size_t)(t + j) * DH);
                        const float4 va = vp[0];
                        const float4 vb = vp[1];
                        acc0 = fmaf(p, va.x, acc0);
                        acc1 = fmaf(p, va.y, acc1);
                        acc2 = fmaf(p, va.z, acc2);
                        acc3 = fmaf(p, va.w, acc3);
                        acc4 = fmaf(p, vb.x, acc4);
                        acc5 = fmaf(p, vb.y, acc5);
                        acc6 = fmaf(p, vb.z, acc6);
                        acc7 = fmaf(p, vb.w, acc7);
                    }
                }
            }
        }
    }

    // out = (2 / l) * acc   (inverted dropout scaling 1/(1-p) = 2)
    const float inv = 2.0f / l;
    float4 o0 = make_float4(acc0 * inv, acc1 * inv, acc2 * inv, acc3 * inv);
    float4 o1 = make_float4(acc4 * inv, acc5 * inv, acc6 * inv, acc7 * inv);
    float4* op = reinterpret_cast<float4*>(out + (size_t)row * DH);
    op[0] = o0;
    op[1] = o1;
}

// ---------------------------------------------------------------------------
extern "C" void kernel_launch(void* const* d_in, const int* in_sizes, int n_in,
                              void* d_out, int out_size) {
    const float* x1 = (const float*)d_in[0];
    const float* x2 = (const float*)d_in[1];
    const float* Wq = (const float*)d_in[2];
    const float* bq = (const float*)d_in[3];
    const float* Wk = (const float*)d_in[4];
    // d_in[5] = bk: contributes only per-row constants -> cancels in softmax
    const float* Wv = (const float*)d_in[6];
    const float* bv = (const float*)d_in[7];
    float* out = (float*)d_out;

    precompute_kernel<<<(NHEAD * SEQ + 255) / 256, 256>>>(x1, x2, Wq, bq, Wk, Wv, bv);

    const int smem = SEQ * (int)sizeof(float4);   // 64 KB -> needs opt-in
    cudaFuncSetAttribute(attn_kernel, cudaFuncAttributeMaxDynamicSharedMemorySize, smem);
    dim3 grid(SEQ / 128, NHEAD);
    attn_kernel<<<grid, 128, smem>>>(x1, out);
}